// round 16
// baseline (speedup 1.0000x reference)
#include <cuda_runtime.h>
#include <cstdint>

// Problem constants
#define L_   12
#define B_   4
#define H_   12
#define S_   785          // seq incl. CLS
#define NP   784          // LayerNorm width
#define KS   588          // 1-based k-th smallest
#define LN_EPS 1e-5f

// Stage-1 tiling (proven R7/R15 config)
#define CH     2                   // row chunks per (b, l, h)
#define ROWS_PER_CHUNK 392         // 784 / CH
#define NPART  (144 * CH)          // 288 partials per b

// Tail: one cluster of 4 CTAs per batch; each CTA owns 196 columns.
#define CLN    4                   // cluster size
#define TCOLS  (NP / CLN)          // 196 columns per CTA
#define KG     8                   // k-subgroups per CTA
#define PER_KG (NPART / KG)        // 36 partials per subgroup

// Deterministic scratch (device globals — no allocation in kernel_launch)
__device__ float g_part1[B_ * NPART * S_];   // ~3.6 MB

// ---------------------------------------------------------------------------
// Kernel 1: streaming column sums (proven 221us config, unchanged).
// ---------------------------------------------------------------------------
__global__ __launch_bounds__(800, 2)
void colsum_kernel(const float* __restrict__ att) {
    const int tid   = threadIdx.x;
    if (tid >= S_) return;
    const int chunk = blockIdx.x;     // 0..CH-1
    const int lh    = blockIdx.y;     // 0..143
    const int b     = blockIdx.z;     // 0..3

    const int l = lh / H_;
    const int h = lh - l * H_;
    const int i0 = 1 + chunk * ROWS_PER_CHUNK;   // skip CLS row (i = 0)

    const size_t base =
        ((((size_t)l * B_ + b) * H_ + h) * S_ + i0) * (size_t)S_ + tid;
    const float* __restrict__ p = att + base;

    float a0 = 0.f, a1 = 0.f, a2 = 0.f, a3 = 0.f;
    float a4 = 0.f, a5 = 0.f, a6 = 0.f, a7 = 0.f;

    #pragma unroll 1
    for (int r = 0; r < ROWS_PER_CHUNK / 8; ++r) {
        a0 += p[0 * S_];
        a1 += p[1 * S_];
        a2 += p[2 * S_];
        a3 += p[3 * S_];
        a4 += p[4 * S_];
        a5 += p[5 * S_];
        a6 += p[6 * S_];
        a7 += p[7 * S_];
        p += 8 * S_;
    }
    // fixed pairwise tree (deterministic)
    const float sum = ((a0 + a1) + (a2 + a3)) + ((a4 + a5) + (a6 + a7));

    g_part1[((size_t)b * NPART + (size_t)lh * CH + chunk) * S_ + tid] = sum;
}

// ---------------------------------------------------------------------------
// Cluster helpers
// ---------------------------------------------------------------------------
__device__ __forceinline__ uint32_t smem_u32(const void* p) {
    uint32_t a;
    asm("{ .reg .u64 t; cvta.to.shared.u64 t, %1; cvt.u32.u64 %0, t; }"
        : "=r"(a) : "l"(p));
    return a;
}
__device__ __forceinline__ uint32_t mapa_rank(uint32_t laddr, uint32_t rank) {
    uint32_t r;
    asm("mapa.shared::cluster.u32 %0, %1, %2;" : "=r"(r) : "r"(laddr), "r"(rank));
    return r;
}
__device__ __forceinline__ void dsmem_st_f32(uint32_t raddr, float v) {
    asm volatile("st.shared::cluster.f32 [%0], %1;" :: "r"(raddr), "f"(v) : "memory");
}
__device__ __forceinline__ float dsmem_ld_f32(uint32_t raddr) {
    float v;
    asm volatile("ld.shared::cluster.f32 %0, [%1];" : "=f"(v) : "r"(raddr) : "memory");
    return v;
}
#define CLUSTER_SYNC() do { \
    asm volatile("barrier.cluster.arrive.aligned;" ::: "memory"); \
    asm volatile("barrier.cluster.wait.aligned;"   ::: "memory"); \
} while (0)

// ---------------------------------------------------------------------------
// Kernel 2 (single-launch tail): cluster of 4 CTAs per batch.
// Phase 1: each CTA collapses 288 partials for its 196 columns (coalesced,
//          L2-hot), keeps s locally, ships s to rank-0 smem via DSMEM.
// Phase 2: rank-0 CTA runs the proven finalize (shuffle LN + 4-round radix
//          select on the monotone uint key; exact k-th value, ties as in
//          sorting), converts the key back to the float threshold, and
//          broadcasts {mu, rstd, thr}.
// Phase 3: every CTA recomputes v for its columns (identical FP expression
//          -> identical bits) and writes the mask. v > thr  <=>  key > prefix.
// All orders fixed -> bitwise deterministic.
// ---------------------------------------------------------------------------
__global__ __launch_bounds__(1024, 1) __cluster_dims__(CLN, 1, 1)
void tail_kernel(const float* __restrict__ gamma,
                 const float* __restrict__ beta,
                 float* __restrict__ out) {
    __shared__ float sm[KG][128];
    __shared__ float s_loc[TCOLS];
    __shared__ float s_all[NP];        // populated in rank 0 only
    __shared__ unsigned skey[NP];
    __shared__ int hist[256];
    __shared__ float wred[32];
    __shared__ float bcast[3];         // mu, rstd, thr (rank 0 writes)
    __shared__ float s_mu, s_rstd;
    __shared__ unsigned s_prefix;
    __shared__ int s_k;

    const int t    = threadIdx.x;
    const int b    = blockIdx.y;
    uint32_t rank;
    asm("mov.u32 %0, %%cluster_ctarank;" : "=r"(rank));

    // ---- Phase 1: partial collapse for this CTA's 196 columns ----
    const int lane = t & 127;
    const int kg   = t >> 7;           // 0..7

    #pragma unroll
    for (int ci = 0; ci < 2; ++ci) {
        const int c = ci * 128 + lane;         // local col 0..255 (guard < 196)
        float s = 0.f;
        if (c < TCOLS) {
            const int gcol = rank * TCOLS + c; // global col 0..783
            // output column gcol = source column (gcol + 1)  (skip CLS)
            const float* __restrict__ src = g_part1 +
                ((size_t)b * NPART + (size_t)kg * PER_KG) * S_ + (gcol + 1);
            #pragma unroll
            for (int k = 0; k < PER_KG; ++k) s += src[(size_t)k * S_];
        }
        sm[kg][lane] = s;
        __syncthreads();

        if (kg == 0 && c < TCOLS) {
            // fixed pairwise tree (deterministic)
            float t0 = sm[0][lane] + sm[1][lane];
            float t1 = sm[2][lane] + sm[3][lane];
            float t2 = sm[4][lane] + sm[5][lane];
            float t3 = sm[6][lane] + sm[7][lane];
            const float val = ((t0 + t1) + (t2 + t3)) * (1.0f / (L_ * H_));
            s_loc[c] = val;
            const int gcol = rank * TCOLS + c;
            // ship to rank-0's s_all[gcol]
            dsmem_st_f32(mapa_rank(smem_u32(&s_all[gcol]), 0), val);
        }
        __syncthreads();
    }

    CLUSTER_SYNC();    // s_all complete & visible in rank 0

    // ---- Phase 2: finalize on rank 0 (1024 threads) ----
    if (rank == 0) {
        const int lane32 = t & 31;
        const int warp   = t >> 5;

        const float s = (t < NP) ? s_all[t] : 0.f;

        // mean: warp shuffle tree (fixed order), then warp-0 combine
        float v = s;
        #pragma unroll
        for (int o = 16; o > 0; o >>= 1) v += __shfl_down_sync(0xFFFFFFFFu, v, o);
        if (lane32 == 0) wred[warp] = v;
        __syncthreads();
        if (warp == 0) {
            float w = wred[lane32];
            #pragma unroll
            for (int o = 16; o > 0; o >>= 1) w += __shfl_down_sync(0xFFFFFFFFu, w, o);
            if (lane32 == 0) s_mu = w / NP;
        }
        __syncthreads();
        const float mu = s_mu;

        // variance
        const float d = (t < NP) ? (s - mu) : 0.f;
        v = d * d;
        #pragma unroll
        for (int o = 16; o > 0; o >>= 1) v += __shfl_down_sync(0xFFFFFFFFu, v, o);
        if (lane32 == 0) wred[warp] = v;
        __syncthreads();
        if (warp == 0) {
            float w = wred[lane32];
            #pragma unroll
            for (int o = 16; o > 0; o >>= 1) w += __shfl_down_sync(0xFFFFFFFFu, w, o);
            if (lane32 == 0) {
                s_rstd = rsqrtf(w / NP + LN_EPS);
                s_prefix = 0u;
                s_k = KS;
            }
        }
        __syncthreads();

        // LN value -> monotone uint key
        unsigned mykey = 0u;
        if (t < NP) {
            const float val = d * s_rstd * gamma[t] + beta[t];
            unsigned u = __float_as_uint(val);
            u = (u & 0x80000000u) ? ~u : (u | 0x80000000u);
            skey[t] = u;
            mykey = u;
        }
        __syncthreads();

        // 4-round radix select (MSB first) for the KS-th smallest key
        #pragma unroll
        for (int r = 0; r < 4; ++r) {
            const int sh = 24 - 8 * r;

            if (t < 256) hist[t] = 0;
            __syncthreads();

            if (t < NP) {
                bool act = (r == 0) ||
                           ((mykey >> (sh + 8)) == (s_prefix >> (sh + 8)));
                if (act) atomicAdd(&hist[(mykey >> sh) & 0xFFu], 1);
            }
            __syncthreads();

            if (t < 32) {
                int c[8], lsum = 0;
                #pragma unroll
                for (int i = 0; i < 8; ++i) { c[i] = hist[t * 8 + i]; lsum += c[i]; }
                int incl = lsum;
                #pragma unroll
                for (int o = 1; o < 32; o <<= 1) {
                    int n = __shfl_up_sync(0xFFFFFFFFu, incl, o);
                    if (t >= o) incl += n;
                }
                const int excl = incl - lsum;
                const int kk = s_k;
                if (excl < kk && kk <= incl) {     // exactly one lane
                    int run = excl, bin = 0, newk = 0;
                    #pragma unroll
                    for (int i = 0; i < 8; ++i) {
                        if (newk == 0 && run + c[i] >= kk) { bin = t * 8 + i; newk = kk - run; }
                        run += c[i];
                    }
                    s_prefix |= (unsigned)bin << sh;
                    s_k = newk;
                }
            }
            __syncthreads();
        }

        if (t == 0) {
            // invert the monotone key transform -> float threshold
            const unsigned key = s_prefix;
            const unsigned bits = (key & 0x80000000u) ? (key & 0x7FFFFFFFu) : ~key;
            bcast[0] = s_mu;
            bcast[1] = s_rstd;
            bcast[2] = __uint_as_float(bits);
        }
    }

    CLUSTER_SYNC();    // bcast visible to all CTAs

    // ---- Phase 3: every CTA writes the mask for its columns ----
    const uint32_t bc = mapa_rank(smem_u32(&bcast[0]), 0);
    const float mu   = dsmem_ld_f32(bc + 0);
    const float rstd = dsmem_ld_f32(bc + 4);
    const float thr  = dsmem_ld_f32(bc + 8);

    if (t < TCOLS) {
        const int gcol = rank * TCOLS + t;
        const float v = (s_loc[t] - mu) * rstd * gamma[gcol] + beta[gcol];
        out[(size_t)b * NP + gcol] = (v > thr) ? 1.0f : 0.0f;
    }

    CLUSTER_SYNC();    // no CTA exits while peers may still read its smem
}

// ---------------------------------------------------------------------------
extern "C" void kernel_launch(void* const* d_in, const int* in_sizes, int n_in,
                              void* d_out, int out_size) {
    const float* att   = (const float*)d_in[0];
    const float* gamma = (const float*)d_in[1];
    const float* beta  = (const float*)d_in[2];
    float* out = (float*)d_out;

    colsum_kernel<<<dim3(CH, 144, B_), 800>>>(att);
    tail_kernel<<<dim3(CLN, B_), 1024>>>(gamma, beta, out);
}